// round 2
// baseline (speedup 1.0000x reference)
#include <cuda_runtime.h>
#include <cstdint>

// ---------------------------------------------------------------------------
// Problem constants
// ---------------------------------------------------------------------------
static constexpr int M_TOTAL = 8192;      // 4 * 2048
static constexpr int N_TOTAL = 11008;
static constexpr int K_TOTAL = 4096;

static constexpr int BM = 128;
static constexpr int BN = 256;
static constexpr int BK = 32;                 // tf32 elements -> 128 B per row
static constexpr int STAGES = 4;
static constexpr int KITERS = K_TOTAL / BK;   // 128

static constexpr int A_STAGE = BM * BK * 4;   // 16 KB
static constexpr int B_STAGE = BN * BK * 4;   // 32 KB
static constexpr int SMEM_BYTES = STAGES * (A_STAGE + B_STAGE) + 1024; // 197632

static constexpr int PID_N = N_TOTAL / BN;    // 43
static constexpr int GROUP_M = 8;             // CTA rasterization group

// ---------------------------------------------------------------------------
// Scratch (device globals: allocation-free)
// ---------------------------------------------------------------------------
__device__ float g_xt[(size_t)M_TOTAL * K_TOTAL];   // tf32-rounded x
__device__ float g_wt[(size_t)N_TOTAL * K_TOTAL];   // tf32-rounded dequant W

__constant__ float c_nf4[16] = {
    -1.0f, -0.6961928009986877f, -0.5250730514526367f, -0.39491748809814453f,
    -0.28444138169288635f, -0.18477343022823334f, -0.09105003625154495f, 0.0f,
    0.07958029955625534f, 0.16093020141124725f, 0.24611230194568634f,
    0.33791524171829224f, 0.44070982933044434f, 0.5626170039176941f,
    0.7229568362236023f, 1.0f};

// ---------------------------------------------------------------------------
// Helpers (baseline PTX only: sm_80-era; NO tcgen05/TMEM)
// ---------------------------------------------------------------------------
__device__ __forceinline__ uint32_t smem_u32(const void* p) {
    uint32_t a;
    asm("{ .reg .u64 t; cvta.to.shared.u64 t, %1; cvt.u32.u64 %0, t; }" : "=r"(a) : "l"(p));
    return a;
}

__device__ __forceinline__ float to_tf32(float x) {
    uint32_t u;
    asm("cvt.rna.tf32.f32 %0, %1;" : "=r"(u) : "f"(x));
    return __uint_as_float(u);
}

__device__ __forceinline__ void cp16(uint32_t dst, const void* src) {
    asm volatile("cp.async.cg.shared.global [%0], [%1], 16;" :: "r"(dst), "l"(src));
}
__device__ __forceinline__ void cp_commit() {
    asm volatile("cp.async.commit_group;" ::: "memory");
}
template <int N>
__device__ __forceinline__ void cp_wait() {
    asm volatile("cp.async.wait_group %0;" :: "n"(N) : "memory");
}

__device__ __forceinline__ void ldsm4(uint32_t* r, uint32_t addr) {
    asm volatile("ldmatrix.sync.aligned.m8n8.x4.shared.b16 {%0,%1,%2,%3}, [%4];"
                 : "=r"(r[0]), "=r"(r[1]), "=r"(r[2]), "=r"(r[3]) : "r"(addr));
}

__device__ __forceinline__ void mma_tf32(float* c, const uint32_t* a,
                                         uint32_t b0, uint32_t b1) {
    asm volatile(
        "mma.sync.aligned.m16n8k8.row.col.f32.tf32.tf32.f32 "
        "{%0,%1,%2,%3}, {%4,%5,%6,%7}, {%8,%9}, {%0,%1,%2,%3};"
        : "+f"(c[0]), "+f"(c[1]), "+f"(c[2]), "+f"(c[3])
        : "r"(a[0]), "r"(a[1]), "r"(a[2]), "r"(a[3]), "r"(b0), "r"(b1));
}

// SW128 swizzle on (row*128 + colb): addr = row*128 + (colb ^ ((row&7)<<4))
#define SWZ(row, colb) ((uint32_t)(row) * 128u + ((uint32_t)(colb) ^ ((((uint32_t)(row)) & 7u) << 4)))

// ---------------------------------------------------------------------------
// Kernel 1: round x to tf32 into g_xt
// ---------------------------------------------------------------------------
__global__ void __launch_bounds__(256) convert_x_kernel(const float* __restrict__ x) {
    size_t i = (size_t)blockIdx.x * 256 + threadIdx.x;   // float4 index
    float4 v = reinterpret_cast<const float4*>(x)[i];
    v.x = to_tf32(v.x); v.y = to_tf32(v.y); v.z = to_tf32(v.z); v.w = to_tf32(v.w);
    reinterpret_cast<float4*>(g_xt)[i] = v;
}

// ---------------------------------------------------------------------------
// Kernel 2: NF4 dequant -> tf32 into g_wt (flat == [N,K] row-major)
// ---------------------------------------------------------------------------
__global__ void __launch_bounds__(256) dequant_w_kernel(const int* __restrict__ q,
                                                        const float* __restrict__ sc) {
    float tv = c_nf4[threadIdx.x & 15];                  // lane l holds nf4[l&15]
    size_t i = (size_t)blockIdx.x * 256 + threadIdx.x;   // int4 pack index
    int4 qq = reinterpret_cast<const int4*>(q)[i];
    float s = __ldg(sc + (i >> 5));                      // 128-elem group = 32 packs
    float4 o;
    o.x = to_tf32(__shfl_sync(0xffffffffu, tv, qq.x & 15) * s);
    o.y = to_tf32(__shfl_sync(0xffffffffu, tv, qq.y & 15) * s);
    o.z = to_tf32(__shfl_sync(0xffffffffu, tv, qq.z & 15) * s);
    o.w = to_tf32(__shfl_sync(0xffffffffu, tv, qq.w & 15) * s);
    reinterpret_cast<float4*>(g_wt)[i] = o;
}

// ---------------------------------------------------------------------------
// Kernel 3: mma.sync tf32 GEMM.  D[m][n] = sum_k A[m,k]*B[n,k] + bias[n]
// 512 threads = 16 warps, warp grid 4(M) x 4(N), warp tile 32x64.
// ---------------------------------------------------------------------------
__device__ __forceinline__ void load_stage(int kiter, int s, int m0, int n0,
                                           uint32_t a_smem, uint32_t b_smem, int tid) {
    const float* asrc = g_xt + (size_t)m0 * K_TOTAL + kiter * BK;
    uint32_t adst = a_smem + s * A_STAGE;
#pragma unroll
    for (int it = 0; it < 2; it++) {                 // 1024 16B chunks / 512 thr
        int idx = tid + it * 512;
        int r = idx >> 3, ch = idx & 7;
        cp16(adst + SWZ(r, ch * 16), asrc + (size_t)r * K_TOTAL + ch * 4);
    }
    const float* bsrc = g_wt + (size_t)n0 * K_TOTAL + kiter * BK;
    uint32_t bdst = b_smem + s * B_STAGE;
#pragma unroll
    for (int it = 0; it < 4; it++) {                 // 2048 chunks / 512 thr
        int idx = tid + it * 512;
        int r = idx >> 3, ch = idx & 7;
        cp16(bdst + SWZ(r, ch * 16), bsrc + (size_t)r * K_TOTAL + ch * 4);
    }
}

__global__ void __launch_bounds__(512, 1) gemm_tf32_kernel(const float* __restrict__ bias,
                                                           float* __restrict__ out) {
    extern __shared__ char smem[];
    uint32_t sb = (smem_u32(smem) + 1023u) & ~1023u;
    uint32_t a_smem = sb;
    uint32_t b_smem = sb + STAGES * A_STAGE;

    int tid = threadIdx.x;
    int lane = tid & 31, wid = tid >> 5;
    int warpM = wid & 3, warpN = wid >> 2;
    int q = lane >> 3, rl = lane & 7;

    // grouped rasterization: keep per-wave working set inside L2
    int pid = blockIdx.x;
    int group = pid / (GROUP_M * PID_N);
    int local = pid % (GROUP_M * PID_N);
    int pid_m = group * GROUP_M + (local & (GROUP_M - 1));
    int pid_n = local >> 3;                       // GROUP_M = 8
    int m0 = pid_m * BM, n0 = pid_n * BN;

    // per-thread ldmatrix row offsets (pre-swizzle xor = rl<<4 for all)
    uint32_t xorv = (uint32_t)rl << 4;
    // A: mt tiles (2). lanes: q0:(+0,k0) q1:(+8,k0) q2:(+0,k0+16B) q3:(+8,k0+16B)
    uint32_t arow0 = (uint32_t)(warpM * 32 + (q & 1) * 8 + rl);
    uint32_t acolq = (uint32_t)((q >> 1) * 16);
    // B: nt2 tiles (4, 16 n each). lanes: q0:(+0,k0) q1:(+0,+16B) q2:(+8,k0) q3:(+8,+16B)
    uint32_t brow0 = (uint32_t)(warpN * 64 + (q >> 1) * 8 + rl);
    uint32_t bcolq = (uint32_t)((q & 1) * 16);

    float c[2][8][4];
#pragma unroll
    for (int i = 0; i < 2; i++)
#pragma unroll
        for (int j = 0; j < 8; j++)
#pragma unroll
            for (int k = 0; k < 4; k++) c[i][j][k] = 0.0f;

    // prologue: fill STAGES-1 stages
#pragma unroll
    for (int j = 0; j < STAGES - 1; j++) {
        load_stage(j, j, m0, n0, a_smem, b_smem, tid);
        cp_commit();
    }

#pragma unroll 1
    for (int i = 0; i < KITERS; i++) {
        int s = i & (STAGES - 1);
        cp_wait<STAGES - 2>();      // own writes for stage i done
        __syncthreads();            // everyone's writes visible; all past compute i-1

        // issue next stage loads first (overlap LDGSTS with math)
        int li = i + STAGES - 1;
        if (li < KITERS) load_stage(li, li & (STAGES - 1), m0, n0, a_smem, b_smem, tid);
        cp_commit();                // unconditional: keeps wait_group counting sound

        uint32_t abase = a_smem + s * A_STAGE;
        uint32_t bbase = b_smem + s * B_STAGE;
#pragma unroll
        for (int ks = 0; ks < 4; ks++) {
            uint32_t colA = ((uint32_t)(ks * 32) + acolq) ^ xorv;
            uint32_t colB = ((uint32_t)(ks * 32) + bcolq) ^ xorv;
            uint32_t a0[4], a1[4];
            ldsm4(a0, abase + arow0 * 128 + colA);
            ldsm4(a1, abase + (arow0 + 16) * 128 + colA);
            uint32_t b[4][4];
#pragma unroll
            for (int nt2 = 0; nt2 < 4; nt2++)
                ldsm4(b[nt2], bbase + (brow0 + nt2 * 16) * 128 + colB);
#pragma unroll
            for (int nt2 = 0; nt2 < 4; nt2++) {
                mma_tf32(c[0][nt2 * 2 + 0], a0, b[nt2][0], b[nt2][1]);
                mma_tf32(c[1][nt2 * 2 + 0], a1, b[nt2][0], b[nt2][1]);
                mma_tf32(c[0][nt2 * 2 + 1], a0, b[nt2][2], b[nt2][3]);
                mma_tf32(c[1][nt2 * 2 + 1], a1, b[nt2][2], b[nt2][3]);
            }
        }
    }

    // epilogue: c layout row = lane/4 (+8), col = 2*(lane%4) (+1)
    int g = lane >> 2, tig = lane & 3;
#pragma unroll
    for (int nt = 0; nt < 8; nt++) {
        int col = n0 + warpN * 64 + nt * 8 + tig * 2;
        float bx = __ldg(bias + col);
        float by = __ldg(bias + col + 1);
#pragma unroll
        for (int mt = 0; mt < 2; mt++) {
            size_t row = (size_t)m0 + warpM * 32 + mt * 16 + g;
            float2 v0 = make_float2(c[mt][nt][0] + bx, c[mt][nt][1] + by);
            float2 v1 = make_float2(c[mt][nt][2] + bx, c[mt][nt][3] + by);
            *reinterpret_cast<float2*>(out + row * N_TOTAL + col) = v0;
            *reinterpret_cast<float2*>(out + (row + 8) * N_TOTAL + col) = v1;
        }
    }
}

// ---------------------------------------------------------------------------
// Launch
// ---------------------------------------------------------------------------
extern "C" void kernel_launch(void* const* d_in, const int* in_sizes, int n_in,
                              void* d_out, int out_size) {
    const float* x = nullptr;
    const int* wq = nullptr;
    const float* ws = nullptr;
    const float* bias = nullptr;
    for (int i = 0; i < n_in; i++) {
        switch (in_sizes[i]) {
            case 33554432: x    = (const float*)d_in[i]; break;  // 4*2048*4096
            case 45088768: wq   = (const int*)d_in[i];   break;  // 11008*4096
            case 352256:   ws   = (const float*)d_in[i]; break;  // groups
            case 11008:    bias = (const float*)d_in[i]; break;
        }
    }

    cudaFuncSetAttribute(gemm_tf32_kernel,
                         cudaFuncAttributeMaxDynamicSharedMemorySize, SMEM_BYTES);

    convert_x_kernel<<<33554432 / 4 / 256, 256>>>(x);        // 32768 blocks
    dequant_w_kernel<<<45088768 / 4 / 256, 256>>>(wq, ws);   // 44032 blocks

    int grid = (M_TOTAL / BM) * (N_TOTAL / BN);              // 64*43 = 2752
    gemm_tf32_kernel<<<grid, 512, SMEM_BYTES>>>(bias, (float*)d_out);
    (void)out_size;
}